// round 8
// baseline (speedup 1.0000x reference)
#include <cuda_runtime.h>
#include <cuda_bf16.h>
#include <cstdint>
#include <cstddef>

// Problem constants
#define BATCH   32
#define TSTEPS  2048
#define INDIM   256
#define HDIM    256
#define GDIM    768            // 3*H
#define OUTDIM  256

// Scratch for xg = x @ W_i + bias : (B*T, 3H) fp32 = 192 MB
__device__ float g_xg[(size_t)BATCH * TSTEPS * GDIM];

// ---------------------------------------------------------------------------
// Helpers (scalar only — every asm form below is proven on sm_100a in a
// passing round)
// ---------------------------------------------------------------------------
__device__ __forceinline__ uint32_t smem_u32(const void* p) {
    uint32_t a;
    asm("{ .reg .u64 t; cvta.to.shared.u64 t, %1; cvt.u32.u64 %0, t; }"
        : "=r"(a) : "l"(p));
    return a;
}

__device__ __forceinline__ void cluster_sync_() {
    asm volatile("barrier.cluster.arrive.aligned;" ::: "memory");
    asm volatile("barrier.cluster.wait.aligned;" ::: "memory");
}

// overflow-safe fast sigmoid / tanh (MUFU-only)
__device__ __forceinline__ float sigmoid_(float x) {
    float e = __expf(-x);
    return __fdividef(1.0f, 1.0f + e);
}
__device__ __forceinline__ float tanh_(float x) {
    float e = __expf(2.0f * x);
    return 1.0f - __fdividef(2.0f, e + 1.0f);
}

__device__ __forceinline__ void mbar_init_(uint32_t addr, uint32_t cnt) {
    asm volatile("mbarrier.init.shared.b64 [%0], %1;" :: "r"(addr), "r"(cnt) : "memory");
}
__device__ __forceinline__ void mbar_arrive_remote_(uint32_t addr) {
    asm volatile("mbarrier.arrive.release.cluster.shared::cluster.b64 _, [%0];"
                 :: "r"(addr) : "memory");
}
__device__ __forceinline__ void bar_wait_(uint32_t mbar, uint32_t parity) {
    uint32_t done;
    asm volatile("{\n\t.reg .pred p;\n\t"
                 "mbarrier.try_wait.parity.acquire.cluster.shared::cta.b64 p, [%1], %2;\n\t"
                 "selp.b32 %0, 1, 0, p;\n\t}"
                 : "=r"(done) : "r"(mbar), "r"(parity) : "memory");
    while (!done) {
        asm volatile("{\n\t.reg .pred p;\n\t"
                     "mbarrier.try_wait.parity.acquire.cluster.shared::cta.b64 p, [%1], %2, 0x989680;\n\t"
                     "selp.b32 %0, 1, 0, p;\n\t}"
                     : "=r"(done) : "r"(mbar), "r"(parity) : "memory");
    }
}

// ---------------------------------------------------------------------------
// Kernel 1: xg = x @ W_i + bias    (M=65536, N=768, K=256)  fp32 tiled SGEMM
// (proven scalar version — measured 677us)
// ---------------------------------------------------------------------------
__global__ __launch_bounds__(256)
void gemm_xg_kernel(const float* __restrict__ X,
                    const float* __restrict__ Wi,
                    const float* __restrict__ bias)
{
    __shared__ __align__(16) float As[16][128];   // transposed A tile
    __shared__ __align__(16) float Bs[16][64];

    const int bm = blockIdx.x * 128;
    const int bn = blockIdx.y * 64;
    const int tid = threadIdx.x;
    const int tx = tid & 15;       // N direction (4 cols each)
    const int ty = tid >> 4;       // M direction (8 rows each)

    float acc[8][4];
#pragma unroll
    for (int i = 0; i < 8; ++i)
#pragma unroll
        for (int j = 0; j < 4; ++j) acc[i][j] = 0.0f;

    for (int k0 = 0; k0 < INDIM; k0 += 16) {
#pragma unroll
        for (int q = 0; q < 2; ++q) {
            int f   = q * 256 + tid;
            int row = f >> 2;
            int k4  = (f & 3) << 2;
            float4 v = *reinterpret_cast<const float4*>(
                X + (size_t)(bm + row) * INDIM + k0 + k4);
            As[k4 + 0][row] = v.x;
            As[k4 + 1][row] = v.y;
            As[k4 + 2][row] = v.z;
            As[k4 + 3][row] = v.w;
        }
        {
            int kr = tid >> 4;
            int c4 = (tid & 15) << 2;
            float4 v = *reinterpret_cast<const float4*>(
                Wi + (size_t)(k0 + kr) * GDIM + bn + c4);
            *reinterpret_cast<float4*>(&Bs[kr][c4]) = v;
        }
        __syncthreads();

#pragma unroll
        for (int kk = 0; kk < 16; ++kk) {
            float4 a0 = *reinterpret_cast<const float4*>(&As[kk][ty * 8]);
            float4 a1 = *reinterpret_cast<const float4*>(&As[kk][ty * 8 + 4]);
            float4 bv = *reinterpret_cast<const float4*>(&Bs[kk][tx * 4]);
            float a[8] = {a0.x, a0.y, a0.z, a0.w, a1.x, a1.y, a1.z, a1.w};
            float bb[4] = {bv.x, bv.y, bv.z, bv.w};
#pragma unroll
            for (int i = 0; i < 8; ++i)
#pragma unroll
                for (int j = 0; j < 4; ++j)
                    acc[i][j] = fmaf(a[i], bb[j], acc[i][j]);
        }
        __syncthreads();
    }

    float4 bv = *reinterpret_cast<const float4*>(bias + bn + tx * 4);
#pragma unroll
    for (int i = 0; i < 8; ++i) {
        int row = bm + ty * 8 + i;
        float4 o;
        o.x = acc[i][0] + bv.x;
        o.y = acc[i][1] + bv.y;
        o.z = acc[i][2] + bv.z;
        o.w = acc[i][3] + bv.w;
        *reinterpret_cast<float4*>(g_xg + (size_t)row * GDIM + bn + tx * 4) = o;
    }
}

// ---------------------------------------------------------------------------
// Kernel 2: GRU recurrence.
// Grid = 128 CTAs, cluster of 4 per batch row, 512 threads/CTA (16 warps,
// 4 warps/SMSP for latency hiding — the R1-vs-R4 lesson).
// Thread (j, ks): j = tid>>3 in [0,64), ks = tid&7 in [0,8).
// Owns all 3 gate columns (r,z,n) of H-index crank*64+j over K slice
// [ks*32,+32): 96 W registers/thread — no spills at the 128-reg cap.
// Granule order rotated by ks for conflict-free LDS.128.
// Per step: FFMA dots -> 3x shfl_xor K-reduce -> gate lanes (ks==0): gate
// math + LOCAL h store -> __syncthreads -> pusher lanes 33/65/97 copy the
// chunk to one remote rank each (32x st.shared::cluster.b64, proven form) +
// release-arrive (count=3) -> states STG + xg prefetch overlap transit ->
// try_wait.acquire.
// ---------------------------------------------------------------------------
__global__ __launch_bounds__(512, 1) __cluster_dims__(4, 1, 1)
void gru_rec_kernel(const float* __restrict__ Wh,
                    float* __restrict__ states)
{
    __shared__ __align__(16) float h_sm[2][HDIM];   // contiguous: buf1 = buf0 + 1KB
    __shared__ __align__(8) unsigned long long bars[2];

    uint32_t crank;
    asm("mov.u32 %0, %%cluster_ctarank;" : "=r"(crank));
    const int b   = blockIdx.x >> 2;
    const int tid = threadIdx.x;
    const int j   = tid >> 3;       // H index within this CTA's 64-chunk
    const int ks  = tid & 7;        // K slice (32 wide)
    const int colbase = (int)crank * 64 + j;

    // ---- Load W_h: 3 gates x 32 K = 96 regs; granule order rotated by ks ----
    // granule gr covers K = ks*32 + rho*4 .. +3, rho = (gr+ks)&7
    float W0[32], W1[32], W2[32];
    {
#pragma unroll
        for (int gr = 0; gr < 8; ++gr) {
            int rho = (gr + ks) & 7;
            int kbase = ks * 32 + rho * 4;
#pragma unroll
            for (int e = 0; e < 4; ++e) {
                const float* wr = Wh + (size_t)(kbase + e) * GDIM;
                W0[gr * 4 + e] = wr[colbase];
                W1[gr * 4 + e] = wr[HDIM + colbase];
                W2[gr * 4 + e] = wr[2 * HDIM + colbase];
            }
        }
    }

    // ---- Init shared state & barriers ----
    if (tid < HDIM) { h_sm[0][tid] = 0.0f; h_sm[1][tid] = 0.0f; }
    const uint32_t bar_l0 = smem_u32(&bars[0]);
    const uint32_t bar_l1 = smem_u32(&bars[1]);
    if (tid == 0) {
        mbar_init_(bar_l0, 3);   // exactly the 3 remote pushers arrive/phase
        mbar_init_(bar_l1, 3);
    }
    __syncthreads();
    cluster_sync_();   // zeros + barrier inits visible cluster-wide

    // ---- Pusher precompute: lanes 33/65/97 -> remote rank (crank+w)&3 ----
    // buffer-1 addresses by constant offset (h_sm contiguous +1024B, bars +8B).
    const bool is_pusher = (tid == 33) || (tid == 65) || (tid == 97);
    uint32_t push_dst0, push_bar0;
    {
        uint32_t w  = (uint32_t)(tid >> 5);           // warp id (1..3 for pushers)
        uint32_t rk = (crank + w) & 3u;
        uint32_t l0 = smem_u32(&h_sm[0][0]);
        uint32_t r0, rb0;
        asm("mapa.shared::cluster.u32 %0, %1, %2;" : "=r"(r0)  : "r"(l0),     "r"(rk));
        asm("mapa.shared::cluster.u32 %0, %1, %2;" : "=r"(rb0) : "r"(bar_l0), "r"(rk));
        push_dst0 = r0 + crank * 64u * 4u;
        push_bar0 = rb0;
    }

    // ---- xg: 2-step-ahead register prefetch (gate lanes only) ----
    const float* xgp = g_xg + (size_t)b * TSTEPS * GDIM + colbase;
    float x0r = 0.f, x0z = 0.f, x0n = 0.f;   // even t
    float x1r = 0.f, x1z = 0.f, x1n = 0.f;   // odd t
    if (ks == 0) {
        x0r = xgp[0];
        x0z = xgp[HDIM];
        x0n = xgp[2 * HDIM];
        const float* x1 = xgp + GDIM;
        x1r = x1[0];
        x1z = x1[HDIM];
        x1n = x1[2 * HDIM];
    }

    const size_t PL = (size_t)TSTEPS * HDIM;                 // plane stride
    float* sp0 = states + (size_t)b * 4 * PL + colbase;      // plane 0, t=0

    int ph0 = 0, ph1 = 0;

    for (int t = 0; t < TSTEPS; ++t) {
        const int cur = t & 1;
        const int nxt = cur ^ 1;

        // gate lanes: start h_old load early (off the post-reduce chain)
        float h_old = 0.f;
        if (ks == 0) h_old = h_sm[cur][colbase];

        // ---- 3 dots of length 32 (rotated conflict-free LDS.128 reads) ----
        const float4* hp = reinterpret_cast<const float4*>(&h_sm[cur][ks * 32]);
        float a0 = 0.f, a1 = 0.f, a2 = 0.f;
        float b0 = 0.f, b1 = 0.f, b2 = 0.f;
#pragma unroll
        for (int gr = 0; gr < 8; ++gr) {
            int rho = (gr + ks) & 7;
            float4 hv = hp[rho];
            a0 = fmaf(W0[gr * 4 + 0], hv.x, a0);
            a1 = fmaf(W1[gr * 4 + 0], hv.x, a1);
            a2 = fmaf(W2[gr * 4 + 0], hv.x, a2);
            b0 = fmaf(W0[gr * 4 + 1], hv.y, b0);
            b1 = fmaf(W1[gr * 4 + 1], hv.y, b1);
            b2 = fmaf(W2[gr * 4 + 1], hv.y, b2);
            a0 = fmaf(W0[gr * 4 + 2], hv.z, a0);
            a1 = fmaf(W1[gr * 4 + 2], hv.z, a1);
            a2 = fmaf(W2[gr * 4 + 2], hv.z, a2);
            b0 = fmaf(W0[gr * 4 + 3], hv.w, b0);
            b1 = fmaf(W1[gr * 4 + 3], hv.w, b1);
            b2 = fmaf(W2[gr * 4 + 3], hv.w, b2);
        }
        float s0 = a0 + b0, s1 = a1 + b1, s2 = a2 + b2;
        // reduce across the 8 K-slices (lane bits 0-2)
        s0 += __shfl_xor_sync(0xffffffffu, s0, 1);
        s1 += __shfl_xor_sync(0xffffffffu, s1, 1);
        s2 += __shfl_xor_sync(0xffffffffu, s2, 1);
        s0 += __shfl_xor_sync(0xffffffffu, s0, 2);
        s1 += __shfl_xor_sync(0xffffffffu, s1, 2);
        s2 += __shfl_xor_sync(0xffffffffu, s2, 2);
        s0 += __shfl_xor_sync(0xffffffffu, s0, 4);
        s1 += __shfl_xor_sync(0xffffffffu, s1, 4);
        s2 += __shfl_xor_sync(0xffffffffu, s2, 4);

        const bool last = (t == TSTEPS - 1);

        float r = 0.f, z = 0.f, n = 0.f, hn = 0.f;
        if (ks == 0) {
            float xr = cur ? x1r : x0r;
            float xz = cur ? x1z : x0z;
            float xn = cur ? x1n : x0n;
            r  = sigmoid_(xr + s0);
            z  = sigmoid_(xz + s1);
            float gg = xn + s2;
            n  = tanh_(fmaf(r, gg, gg));                // tanh(gn + r*gn)
            hn = fmaf(z, h_old - n, n);                 // (1-z)n + z h
            h_sm[nxt][colbase] = hn;                    // LOCAL store only
        }

        if (!last) {
            __syncthreads();   // local STS drain only (fast)

            if (is_pusher) {
                // copy my CTA's 64-float chunk to ONE remote rank: 32 x b64
                const unsigned long long* src =
                    reinterpret_cast<const unsigned long long*>(&h_sm[nxt][(int)crank * 64]);
                const uint32_t dst = push_dst0 + (uint32_t)nxt * 1024u;
#pragma unroll
                for (int i = 0; i < 32; ++i) {
                    unsigned long long v = src[i];
                    asm volatile("st.shared::cluster.b64 [%0], %1;"
                                 :: "r"(dst + (uint32_t)i * 8u), "l"(v) : "memory");
                }
                mbar_arrive_remote_(push_bar0 + (uint32_t)nxt * 8u);  // release
            }
        }

        // ---- off-critical-path: states STG + xg prefetch for t+2 ----
        if (ks == 0) {
            float* sp = sp0 + (size_t)t * HDIM;
            sp[0]      = hn;
            sp[PL]     = r;
            sp[2 * PL] = z;
            sp[3 * PL] = n;
            if (t + 2 < TSTEPS) {
                const float* xq = xgp + (size_t)(t + 2) * GDIM;
                if (cur) { x1r = xq[0]; x1z = xq[HDIM]; x1n = xq[2 * HDIM]; }
                else     { x0r = xq[0]; x0z = xq[HDIM]; x0n = xq[2 * HDIM]; }
            }
        }

        if (!last) {
            if (nxt) { bar_wait_(bar_l1, (uint32_t)ph1); ph1 ^= 1; }
            else     { bar_wait_(bar_l0, (uint32_t)ph0); ph0 ^= 1; }
        }
    }
}

// ---------------------------------------------------------------------------
// Kernel 3: output = h_last @ fc_w + fc_b   (32 x 256, K=256) — tiny
// ---------------------------------------------------------------------------
__global__ __launch_bounds__(256)
void fc_kernel(const float* __restrict__ states,
               const float* __restrict__ fc_w,
               const float* __restrict__ fc_b,
               float* __restrict__ out)
{
    const int b = blockIdx.x;
    const int o = threadIdx.x;
    const float* h = states + (((size_t)b * 4 + 0) * TSTEPS + (TSTEPS - 1)) * HDIM;
    float a0 = 0.f, a1 = 0.f, a2 = 0.f, a3 = 0.f;
#pragma unroll 8
    for (int k = 0; k < HDIM; k += 4) {
        a0 = fmaf(h[k + 0], fc_w[(size_t)(k + 0) * OUTDIM + o], a0);
        a1 = fmaf(h[k + 1], fc_w[(size_t)(k + 1) * OUTDIM + o], a1);
        a2 = fmaf(h[k + 2], fc_w[(size_t)(k + 2) * OUTDIM + o], a2);
        a3 = fmaf(h[k + 3], fc_w[(size_t)(k + 3) * OUTDIM + o], a3);
    }
    out[(size_t)b * OUTDIM + o] = (a0 + a1) + (a2 + a3) + fc_b[o];
}

// ---------------------------------------------------------------------------
// Launch
// ---------------------------------------------------------------------------
extern "C" void kernel_launch(void* const* d_in, const int* in_sizes, int n_in,
                              void* d_out, int out_size)
{
    const float* x    = (const float*)d_in[0];
    const float* Wi   = (const float*)d_in[1];
    const float* Wh   = (const float*)d_in[2];
    const float* bias = (const float*)d_in[3];
    const float* fcw  = (const float*)d_in[4];
    const float* fcb  = (const float*)d_in[5];

    float* out    = (float*)d_out;                 // (32, 256)
    float* states = out + (size_t)BATCH * OUTDIM;  // (32, 4, 2048, 256)

    dim3 ggrid((BATCH * TSTEPS) / 128, GDIM / 64);
    gemm_xg_kernel<<<ggrid, 256>>>(x, Wi, bias);

    gru_rec_kernel<<<BATCH * 4, 512>>>(Wh, states);

    fc_kernel<<<BATCH, 256>>>(states, fcw, fcb, out);
}

// round 9
// speedup vs baseline: 1.0949x; 1.0949x over previous
#include <cuda_runtime.h>
#include <cuda_bf16.h>
#include <cstdint>
#include <cstddef>

// Problem constants
#define BATCH   32
#define TSTEPS  2048
#define INDIM   256
#define HDIM    256
#define GDIM    768            // 3*H
#define OUTDIM  256

// Scratch for xg = x @ W_i + bias : (B*T, 3H) fp32 = 192 MB
__device__ float g_xg[(size_t)BATCH * TSTEPS * GDIM];

// ---------------------------------------------------------------------------
// Helpers (all asm forms proven on sm_100a in passing rounds)
// ---------------------------------------------------------------------------
__device__ __forceinline__ uint32_t smem_u32(const void* p) {
    uint32_t a;
    asm("{ .reg .u64 t; cvta.to.shared.u64 t, %1; cvt.u32.u64 %0, t; }"
        : "=r"(a) : "l"(p));
    return a;
}

__device__ __forceinline__ void cluster_sync_() {
    asm volatile("barrier.cluster.arrive.aligned;" ::: "memory");
    asm volatile("barrier.cluster.wait.aligned;" ::: "memory");
}

// overflow-safe fast sigmoid / tanh (MUFU-only)
__device__ __forceinline__ float sigmoid_(float x) {
    float e = __expf(-x);
    return __fdividef(1.0f, 1.0f + e);
}
__device__ __forceinline__ float tanh_(float x) {
    float e = __expf(2.0f * x);
    return 1.0f - __fdividef(2.0f, e + 1.0f);
}

__device__ __forceinline__ void mbar_init_(uint32_t addr, uint32_t cnt) {
    asm volatile("mbarrier.init.shared.b64 [%0], %1;" :: "r"(addr), "r"(cnt) : "memory");
}
__device__ __forceinline__ void mbar_arrive_remote_(uint32_t addr) {
    asm volatile("mbarrier.arrive.release.cluster.shared::cluster.b64 _, [%0];"
                 :: "r"(addr) : "memory");
}
__device__ __forceinline__ void bar_wait_(uint32_t mbar, uint32_t parity) {
    uint32_t done;
    asm volatile("{\n\t.reg .pred p;\n\t"
                 "mbarrier.try_wait.parity.acquire.cluster.shared::cta.b64 p, [%1], %2;\n\t"
                 "selp.b32 %0, 1, 0, p;\n\t}"
                 : "=r"(done) : "r"(mbar), "r"(parity) : "memory");
    while (!done) {
        asm volatile("{\n\t.reg .pred p;\n\t"
                     "mbarrier.try_wait.parity.acquire.cluster.shared::cta.b64 p, [%1], %2, 0x989680;\n\t"
                     "selp.b32 %0, 1, 0, p;\n\t}"
                     : "=r"(done) : "r"(mbar), "r"(parity) : "memory");
    }
}

// ---------------------------------------------------------------------------
// Kernel 1: xg = x @ W_i + bias    (M=65536, N=768, K=256)  fp32 tiled SGEMM
// (proven scalar version — measured ~677us)
// ---------------------------------------------------------------------------
__global__ __launch_bounds__(256)
void gemm_xg_kernel(const float* __restrict__ X,
                    const float* __restrict__ Wi,
                    const float* __restrict__ bias)
{
    __shared__ __align__(16) float As[16][128];   // transposed A tile
    __shared__ __align__(16) float Bs[16][64];

    const int bm = blockIdx.x * 128;
    const int bn = blockIdx.y * 64;
    const int tid = threadIdx.x;
    const int tx = tid & 15;       // N direction (4 cols each)
    const int ty = tid >> 4;       // M direction (8 rows each)

    float acc[8][4];
#pragma unroll
    for (int i = 0; i < 8; ++i)
#pragma unroll
        for (int j = 0; j < 4; ++j) acc[i][j] = 0.0f;

    for (int k0 = 0; k0 < INDIM; k0 += 16) {
#pragma unroll
        for (int q = 0; q < 2; ++q) {
            int f   = q * 256 + tid;
            int row = f >> 2;
            int k4  = (f & 3) << 2;
            float4 v = *reinterpret_cast<const float4*>(
                X + (size_t)(bm + row) * INDIM + k0 + k4);
            As[k4 + 0][row] = v.x;
            As[k4 + 1][row] = v.y;
            As[k4 + 2][row] = v.z;
            As[k4 + 3][row] = v.w;
        }
        {
            int kr = tid >> 4;
            int c4 = (tid & 15) << 2;
            float4 v = *reinterpret_cast<const float4*>(
                Wi + (size_t)(k0 + kr) * GDIM + bn + c4);
            *reinterpret_cast<float4*>(&Bs[kr][c4]) = v;
        }
        __syncthreads();

#pragma unroll
        for (int kk = 0; kk < 16; ++kk) {
            float4 a0 = *reinterpret_cast<const float4*>(&As[kk][ty * 8]);
            float4 a1 = *reinterpret_cast<const float4*>(&As[kk][ty * 8 + 4]);
            float4 bv = *reinterpret_cast<const float4*>(&Bs[kk][tx * 4]);
            float a[8] = {a0.x, a0.y, a0.z, a0.w, a1.x, a1.y, a1.z, a1.w};
            float bb[4] = {bv.x, bv.y, bv.z, bv.w};
#pragma unroll
            for (int i = 0; i < 8; ++i)
#pragma unroll
                for (int j = 0; j < 4; ++j)
                    acc[i][j] = fmaf(a[i], bb[j], acc[i][j]);
        }
        __syncthreads();
    }

    float4 bv = *reinterpret_cast<const float4*>(bias + bn + tx * 4);
#pragma unroll
    for (int i = 0; i < 8; ++i) {
        int row = bm + ty * 8 + i;
        float4 o;
        o.x = acc[i][0] + bv.x;
        o.y = acc[i][1] + bv.y;
        o.z = acc[i][2] + bv.z;
        o.w = acc[i][3] + bv.w;
        *reinterpret_cast<float4*>(g_xg + (size_t)row * GDIM + bn + tx * 4) = o;
    }
}

// ---------------------------------------------------------------------------
// Kernel 2: GRU recurrence with PER-CHUNK dependency tracking.
// Grid = 128 CTAs, cluster of 4 per batch row, 512 threads/CTA (16 warps).
// Thread tid = ks*64 + j  (ks = tid>>6 in [0,8), j = tid&63).
// Owns all 3 gate columns of H-index crank*64+j over K slice [ks*32,+32)
// (96 W regs). ks is CONSTANT within a warp -> warp w needs only h-chunk
// w>>2; local chunk needs no wait, remote chunks have their own count=1
// mbarrier per buffer -> fabric transit overlaps local dot issue.
// h reads are pure LDS broadcast (all lanes same address).
// Reduction via smem partials (conflict-free), gates on 64 threads.
// ---------------------------------------------------------------------------
__global__ __launch_bounds__(512, 1) __cluster_dims__(4, 1, 1)
void gru_rec_kernel(const float* __restrict__ Wh,
                    float* __restrict__ states)
{
    __shared__ __align__(16) float h_sm[2][HDIM];       // buf1 = buf0 + 1KB
    __shared__ __align__(16) float part[3 * 8 * 64];    // [gate][ks][j] partials
    __shared__ __align__(8) unsigned long long bars[8]; // [chunk][buf]

    uint32_t crank;
    asm("mov.u32 %0, %%cluster_ctarank;" : "=r"(crank));
    const int b   = blockIdx.x >> 2;
    const int tid = threadIdx.x;
    const int ks  = tid >> 6;        // K slice (32 wide), constant per warp-pair
    const int j   = tid & 63;        // H index within this CTA's 64-chunk
    const int mychunk = ks >> 1;     // source chunk of my K slice
    const int colbase = (int)crank * 64 + j;

    // ---- Load W_h: 3 gates x 32 K = 96 regs ----
    float W0[32], W1[32], W2[32];
    {
        const int k0 = ks * 32;
#pragma unroll
        for (int e = 0; e < 32; ++e) {
            const float* wr = Wh + (size_t)(k0 + e) * GDIM;
            W0[e] = wr[colbase];
            W1[e] = wr[HDIM + colbase];
            W2[e] = wr[2 * HDIM + colbase];
        }
    }

    // ---- Init shared state & barriers ----
    if (tid < HDIM) { h_sm[0][tid] = 0.0f; h_sm[1][tid] = 0.0f; }
    const uint32_t bars_base = smem_u32(&bars[0]);
    if (tid < 8) mbar_init_(bars_base + (uint32_t)tid * 8u, 1);  // count=1 each
    __syncthreads();
    cluster_sync_();   // zeros + barrier inits visible cluster-wide

    // ---- My wait barrier (if my chunk is remote): bars[mychunk][buf] ----
    const bool need_wait = (mychunk != (int)crank);
    const uint32_t waitbar0 = bars_base + (uint32_t)(mychunk * 2) * 8u;  // buf0; buf1 = +8

    // ---- Pushers: tid 128 (warp4), 256 (warp8), 384 (warp12) ----
    // tid 128*q pushes to rank (crank+q)&3, into that rank's bars[crank][buf]
    const bool is_pusher = (tid == 128) || (tid == 256) || (tid == 384);
    uint32_t push_dst0 = 0, push_bar0 = 0;
    if (is_pusher) {
        uint32_t q  = (uint32_t)tid >> 7;             // 1,2,3
        uint32_t rk = (crank + q) & 3u;
        uint32_t l0 = smem_u32(&h_sm[0][0]);
        uint32_t r0, rb;
        asm("mapa.shared::cluster.u32 %0, %1, %2;" : "=r"(r0) : "r"(l0),        "r"(rk));
        asm("mapa.shared::cluster.u32 %0, %1, %2;" : "=r"(rb) : "r"(bars_base), "r"(rk));
        push_dst0 = r0 + crank * 64u * 4u;            // my chunk slot in rank rk
        push_bar0 = rb + (crank * 2u) * 8u;           // rank rk's bars[crank][0]
    }

    // ---- xg: 2-step-ahead register prefetch (gate threads = tid<64) ----
    const float* xgp = g_xg + (size_t)b * TSTEPS * GDIM + colbase;
    float x0r = 0.f, x0z = 0.f, x0n = 0.f;   // even t
    float x1r = 0.f, x1z = 0.f, x1n = 0.f;   // odd t
    if (tid < 64) {
        x0r = xgp[0];
        x0z = xgp[HDIM];
        x0n = xgp[2 * HDIM];
        const float* x1 = xgp + GDIM;
        x1r = x1[0];
        x1z = x1[HDIM];
        x1n = x1[2 * HDIM];
    }

    const size_t PL = (size_t)TSTEPS * HDIM;                 // plane stride
    float* sp0 = states + (size_t)b * 4 * PL + colbase;      // plane 0, t=0

    int ph0 = 0, ph1 = 0;   // parity per buffer for my wait barrier

    for (int t = 0; t < TSTEPS; ++t) {
        const int cur = t & 1;
        const int nxt = cur ^ 1;
        const bool last = (t == TSTEPS - 1);

        // ---- wait for my chunk (remote only; t=0 reads zeroed buffers) ----
        if (t > 0 && need_wait) {
            if (cur) { bar_wait_(waitbar0 + 8u, (uint32_t)ph1); ph1 ^= 1; }
            else     { bar_wait_(waitbar0,      (uint32_t)ph0); ph0 ^= 1; }
        }

        // ---- 3 dots of length 32; h reads are warp-broadcast LDS.128 ----
        const float4* hp = reinterpret_cast<const float4*>(&h_sm[cur][ks * 32]);
        float a0 = 0.f, a1 = 0.f, a2 = 0.f;
        float b0 = 0.f, b1 = 0.f, b2 = 0.f;
#pragma unroll
        for (int g4 = 0; g4 < 8; ++g4) {
            float4 hv = hp[g4];
            a0 = fmaf(W0[g4 * 4 + 0], hv.x, a0);
            a1 = fmaf(W1[g4 * 4 + 0], hv.x, a1);
            a2 = fmaf(W2[g4 * 4 + 0], hv.x, a2);
            b0 = fmaf(W0[g4 * 4 + 1], hv.y, b0);
            b1 = fmaf(W1[g4 * 4 + 1], hv.y, b1);
            b2 = fmaf(W2[g4 * 4 + 1], hv.y, b2);
            a0 = fmaf(W0[g4 * 4 + 2], hv.z, a0);
            a1 = fmaf(W1[g4 * 4 + 2], hv.z, a1);
            a2 = fmaf(W2[g4 * 4 + 2], hv.z, a2);
            b0 = fmaf(W0[g4 * 4 + 3], hv.w, b0);
            b1 = fmaf(W1[g4 * 4 + 3], hv.w, b1);
            b2 = fmaf(W2[g4 * 4 + 3], hv.w, b2);
        }
        // ---- write partials: part[g][ks][j], j contiguous per warp ----
        part[0 * 512 + ks * 64 + j] = a0 + b0;
        part[1 * 512 + ks * 64 + j] = a1 + b1;
        part[2 * 512 + ks * 64 + j] = a2 + b2;

        __syncthreads();   // BAR#1: partials visible

        // ---- gates on 64 threads (tid<64, j = tid) ----
        float r = 0.f, z = 0.f, n = 0.f, hn = 0.f;
        if (tid < 64) {
            float s0 = 0.f, s1 = 0.f, s2 = 0.f;
#pragma unroll
            for (int k = 0; k < 8; ++k) {
                s0 += part[0 * 512 + k * 64 + j];
                s1 += part[1 * 512 + k * 64 + j];
                s2 += part[2 * 512 + k * 64 + j];
            }
            float xr = cur ? x1r : x0r;
            float xz = cur ? x1z : x0z;
            float xn = cur ? x1n : x0n;
            r  = sigmoid_(xr + s0);
            z  = sigmoid_(xz + s1);
            float gg = xn + s2;
            n  = tanh_(fmaf(r, gg, gg));                // tanh(gn + r*gn)
            float h_old = h_sm[cur][colbase];
            hn = fmaf(z, h_old - n, n);                 // (1-z)n + z h
            h_sm[nxt][colbase] = hn;                    // LOCAL store only
        }

        __syncthreads();   // BAR#2: h_sm[nxt] local chunk complete

        if (!last && is_pusher) {
            // push my CTA's 64-float chunk to my remote rank: 32 x b64
            const unsigned long long* src =
                reinterpret_cast<const unsigned long long*>(&h_sm[nxt][(int)crank * 64]);
            const uint32_t dst = push_dst0 + (uint32_t)nxt * 1024u;
#pragma unroll
            for (int i = 0; i < 32; ++i) {
                unsigned long long v = src[i];
                asm volatile("st.shared::cluster.b64 [%0], %1;"
                             :: "r"(dst + (uint32_t)i * 8u), "l"(v) : "memory");
            }
            mbar_arrive_remote_(push_bar0 + (uint32_t)nxt * 8u);  // release
        }

        // ---- off-critical-path: states STG + xg prefetch for t+2 ----
        if (tid < 64) {
            float* sp = sp0 + (size_t)t * HDIM;
            sp[0]      = hn;
            sp[PL]     = r;
            sp[2 * PL] = z;
            sp[3 * PL] = n;
            if (t + 2 < TSTEPS) {
                const float* xq = xgp + (size_t)(t + 2) * GDIM;
                if (cur) { x1r = xq[0]; x1z = xq[HDIM]; x1n = xq[2 * HDIM]; }
                else     { x0r = xq[0]; x0z = xq[HDIM]; x0n = xq[2 * HDIM]; }
            }
        }
    }
}

// ---------------------------------------------------------------------------
// Kernel 3: output = h_last @ fc_w + fc_b   (32 x 256, K=256) — tiny
// ---------------------------------------------------------------------------
__global__ __launch_bounds__(256)
void fc_kernel(const float* __restrict__ states,
               const float* __restrict__ fc_w,
               const float* __restrict__ fc_b,
               float* __restrict__ out)
{
    const int b = blockIdx.x;
    const int o = threadIdx.x;
    const float* h = states + (((size_t)b * 4 + 0) * TSTEPS + (TSTEPS - 1)) * HDIM;
    float a0 = 0.f, a1 = 0.f, a2 = 0.f, a3 = 0.f;
#pragma unroll 8
    for (int k = 0; k < HDIM; k += 4) {
        a0 = fmaf(h[k + 0], fc_w[(size_t)(k + 0) * OUTDIM + o], a0);
        a1 = fmaf(h[k + 1], fc_w[(size_t)(k + 1) * OUTDIM + o], a1);
        a2 = fmaf(h[k + 2], fc_w[(size_t)(k + 2) * OUTDIM + o], a2);
        a3 = fmaf(h[k + 3], fc_w[(size_t)(k + 3) * OUTDIM + o], a3);
    }
    out[(size_t)b * OUTDIM + o] = (a0 + a1) + (a2 + a3) + fc_b[o];
}

// ---------------------------------------------------------------------------
// Launch
// ---------------------------------------------------------------------------
extern "C" void kernel_launch(void* const* d_in, const int* in_sizes, int n_in,
                              void* d_out, int out_size)
{
    const float* x    = (const float*)d_in[0];
    const float* Wi   = (const float*)d_in[1];
    const float* Wh   = (const float*)d_in[2];
    const float* bias = (const float*)d_in[3];
    const float* fcw  = (const float*)d_in[4];
    const float* fcb  = (const float*)d_in[5];

    float* out    = (float*)d_out;                 // (32, 256)
    float* states = out + (size_t)BATCH * OUTDIM;  // (32, 4, 2048, 256)

    dim3 ggrid((BATCH * TSTEPS) / 128, GDIM / 64);
    gemm_xg_kernel<<<ggrid, 256>>>(x, Wi, bias);

    gru_rec_kernel<<<BATCH * 4, 512>>>(Wh, states);

    fc_kernel<<<BATCH, 256>>>(states, fcw, fcb, out);
}

// round 10
// speedup vs baseline: 1.2210x; 1.1152x over previous
#include <cuda_runtime.h>
#include <cuda_bf16.h>
#include <cstdint>
#include <cstddef>

// Problem constants
#define BATCH   32
#define TSTEPS  2048
#define INDIM   256
#define HDIM    256
#define GDIM    768            // 3*H
#define OUTDIM  256

// Scratch for xg = x @ W_i + bias : (B*T, 3H) fp32 = 192 MB
__device__ float g_xg[(size_t)BATCH * TSTEPS * GDIM];

// ---------------------------------------------------------------------------
// Helpers (all asm forms proven on sm_100a in passing rounds)
// ---------------------------------------------------------------------------
__device__ __forceinline__ uint32_t smem_u32(const void* p) {
    uint32_t a;
    asm("{ .reg .u64 t; cvta.to.shared.u64 t, %1; cvt.u32.u64 %0, t; }"
        : "=r"(a) : "l"(p));
    return a;
}

__device__ __forceinline__ void cluster_arrive_() {
    asm volatile("barrier.cluster.arrive.aligned;" ::: "memory");
}
__device__ __forceinline__ void cluster_wait_() {
    asm volatile("barrier.cluster.wait.aligned;" ::: "memory");
}

// overflow-safe fast sigmoid / tanh (MUFU-only)
__device__ __forceinline__ float sigmoid_(float x) {
    float e = __expf(-x);
    return __fdividef(1.0f, 1.0f + e);
}
__device__ __forceinline__ float tanh_(float x) {
    float e = __expf(2.0f * x);
    return 1.0f - __fdividef(2.0f, e + 1.0f);
}

// ---------------------------------------------------------------------------
// Kernel 1: xg = x @ W_i + bias    (M=65536, N=768, K=256)  fp32 tiled SGEMM
// (proven scalar version — measured ~677us)
// ---------------------------------------------------------------------------
__global__ __launch_bounds__(256)
void gemm_xg_kernel(const float* __restrict__ X,
                    const float* __restrict__ Wi,
                    const float* __restrict__ bias)
{
    __shared__ __align__(16) float As[16][128];   // transposed A tile
    __shared__ __align__(16) float Bs[16][64];

    const int bm = blockIdx.x * 128;
    const int bn = blockIdx.y * 64;
    const int tid = threadIdx.x;
    const int tx = tid & 15;       // N direction (4 cols each)
    const int ty = tid >> 4;       // M direction (8 rows each)

    float acc[8][4];
#pragma unroll
    for (int i = 0; i < 8; ++i)
#pragma unroll
        for (int j = 0; j < 4; ++j) acc[i][j] = 0.0f;

    for (int k0 = 0; k0 < INDIM; k0 += 16) {
#pragma unroll
        for (int q = 0; q < 2; ++q) {
            int f   = q * 256 + tid;
            int row = f >> 2;
            int k4  = (f & 3) << 2;
            float4 v = *reinterpret_cast<const float4*>(
                X + (size_t)(bm + row) * INDIM + k0 + k4);
            As[k4 + 0][row] = v.x;
            As[k4 + 1][row] = v.y;
            As[k4 + 2][row] = v.z;
            As[k4 + 3][row] = v.w;
        }
        {
            int kr = tid >> 4;
            int c4 = (tid & 15) << 2;
            float4 v = *reinterpret_cast<const float4*>(
                Wi + (size_t)(k0 + kr) * GDIM + bn + c4);
            *reinterpret_cast<float4*>(&Bs[kr][c4]) = v;
        }
        __syncthreads();

#pragma unroll
        for (int kk = 0; kk < 16; ++kk) {
            float4 a0 = *reinterpret_cast<const float4*>(&As[kk][ty * 8]);
            float4 a1 = *reinterpret_cast<const float4*>(&As[kk][ty * 8 + 4]);
            float4 bv = *reinterpret_cast<const float4*>(&Bs[kk][tx * 4]);
            float a[8] = {a0.x, a0.y, a0.z, a0.w, a1.x, a1.y, a1.z, a1.w};
            float bb[4] = {bv.x, bv.y, bv.z, bv.w};
#pragma unroll
            for (int i = 0; i < 8; ++i)
#pragma unroll
                for (int j = 0; j < 4; ++j)
                    acc[i][j] = fmaf(a[i], bb[j], acc[i][j]);
        }
        __syncthreads();
    }

    float4 bv = *reinterpret_cast<const float4*>(bias + bn + tx * 4);
#pragma unroll
    for (int i = 0; i < 8; ++i) {
        int row = bm + ty * 8 + i;
        float4 o;
        o.x = acc[i][0] + bv.x;
        o.y = acc[i][1] + bv.y;
        o.z = acc[i][2] + bv.z;
        o.w = acc[i][3] + bv.w;
        *reinterpret_cast<float4*>(g_xg + (size_t)row * GDIM + bn + tx * 4) = o;
    }
}

// ---------------------------------------------------------------------------
// Kernel 2: GRU recurrence — R1's measured-best skeleton with 3 targeted
// fixes: (a) conflict-free rotated LDS (half-1 granule order +1), (b) MUFU
// gates, (c) arrive/wait split so states-STG + 2-deep xg prefetch overlap
// the cluster barrier.
// Grid = 128 CTAs, cluster of 4 per batch row, 384 threads/CTA.
// Thread (pairId, half): pairId=tid>>1 in [0,192) -> (gate, jj); half=tid&1
// is the K half (128 wide). W half-column in 128 registers.
// Per step: dots -> shfl(1) -> g_sm partials -> BAR -> gate threads (tid<64)
// do gates + per-lane st.shared::cluster to all 4 ranks -> cluster.arrive ->
// STG/prefetch -> cluster.wait.
// ---------------------------------------------------------------------------
__global__ __launch_bounds__(384, 1) __cluster_dims__(4, 1, 1)
void gru_rec_kernel(const float* __restrict__ Wh,
                    float* __restrict__ states)
{
    __shared__ __align__(16) float h_sm[2][HDIM];   // buf1 = buf0 + 1024B
    __shared__ __align__(16) float g_sm[192];

    uint32_t crank;
    asm("mov.u32 %0, %%cluster_ctarank;" : "=r"(crank));
    const int b      = blockIdx.x >> 2;
    const int tid    = threadIdx.x;
    const int half   = tid & 1;       // K half: [0,128) or [128,256)
    const int pairId = tid >> 1;      // 0..191
    const int gate   = pairId >> 6;   // 0..2
    const int jj     = pairId & 63;   // H index within chunk
    const int col    = gate * HDIM + (int)crank * 64 + jj;  // W_h column

    // ---- W half-column in 128 regs, granule order rotated by `half` ----
    // granule g covers K = half*128 + rho*4 .. +3, rho = (g + half) & 31
    float W[128];
    {
#pragma unroll
        for (int g = 0; g < 32; ++g) {
            int rho = (g + half) & 31;
            int kbase = half * 128 + rho * 4;
#pragma unroll
            for (int e = 0; e < 4; ++e)
                W[g * 4 + e] = Wh[(size_t)(kbase + e) * GDIM + col];
        }
    }

    // ---- init ----
    if (tid < HDIM) { h_sm[0][tid] = 0.0f; h_sm[1][tid] = 0.0f; }
    __syncthreads();
    cluster_arrive_();
    cluster_wait_();   // zeros visible cluster-wide

    // ---- gate threads (tid<64): remote h slots in all 4 ranks (buf0) ----
    uint32_t dst0[4];
    {
        uint32_t l0 = smem_u32(&h_sm[0][(int)crank * 64 + (tid & 63)]);
#pragma unroll
        for (int rk = 0; rk < 4; ++rk) {
            asm("mapa.shared::cluster.u32 %0, %1, %2;"
                : "=r"(dst0[rk]) : "r"(l0), "r"(rk));
        }
    }

    // ---- xg: 2-step-ahead register prefetch (gate threads, colb=crank*64+tid) ----
    const float* xgp = g_xg + (size_t)b * TSTEPS * GDIM + (int)crank * 64 + (tid & 63);
    float x0r = 0.f, x0z = 0.f, x0n = 0.f;   // even t
    float x1r = 0.f, x1z = 0.f, x1n = 0.f;   // odd t
    if (tid < 64) {
        x0r = xgp[0];
        x0z = xgp[HDIM];
        x0n = xgp[2 * HDIM];
        const float* x1 = xgp + GDIM;
        x1r = x1[0];
        x1z = x1[HDIM];
        x1n = x1[2 * HDIM];
    }

    const size_t PL = (size_t)TSTEPS * HDIM;
    float* sp0 = states + (size_t)b * 4 * PL + (int)crank * 64 + (tid & 63);

    for (int t = 0; t < TSTEPS; ++t) {
        const int cur = t & 1;
        const int nxt = cur ^ 1;
        const bool last = (t == TSTEPS - 1);

        // ---- dot over my K half (rotated conflict-free LDS.128) ----
        const float4* hp = reinterpret_cast<const float4*>(&h_sm[cur][half * 128]);
        float a0 = 0.f, a1 = 0.f, a2 = 0.f, a3 = 0.f;
#pragma unroll
        for (int g = 0; g < 32; ++g) {
            int rho = (g + half) & 31;
            float4 hv = hp[rho];
            a0 = fmaf(W[g * 4 + 0], hv.x, a0);
            a1 = fmaf(W[g * 4 + 1], hv.y, a1);
            a2 = fmaf(W[g * 4 + 2], hv.z, a2);
            a3 = fmaf(W[g * 4 + 3], hv.w, a3);
        }
        float s = (a0 + a1) + (a2 + a3);
        s += __shfl_xor_sync(0xffffffffu, s, 1);   // combine the two halves

        if (half == 0) g_sm[pairId] = s;           // raw partial (xg added below)
        __syncthreads();                           // partials visible

        // ---- gates on 64 threads ----
        float r = 0.f, z = 0.f, n = 0.f, hn = 0.f;
        if (tid < 64) {
            float s0 = g_sm[tid];
            float s1 = g_sm[64 + tid];
            float s2 = g_sm[128 + tid];
            float xr = cur ? x1r : x0r;
            float xz = cur ? x1z : x0z;
            float xn = cur ? x1n : x0n;
            r  = sigmoid_(xr + s0);
            z  = sigmoid_(xz + s1);
            float gg = xn + s2;
            n  = tanh_(fmaf(r, gg, gg));           // tanh(gn + r*gn)
            float h_old = h_sm[cur][(int)crank * 64 + tid];
            hn = fmaf(z, h_old - n, n);            // (1-z)n + z h

            if (!last) {
                // write h into next buffer of all 4 ranks (incl. self)
                const uint32_t boff = (uint32_t)nxt * 1024u;
#pragma unroll
                for (int rk = 0; rk < 4; ++rk) {
                    asm volatile("st.shared::cluster.f32 [%0], %1;"
                                 :: "r"(dst0[rk] + boff), "f"(hn) : "memory");
                }
            }
        }

        if (!last) cluster_arrive_();   // release: orders the stores above

        // ---- overlapped with barrier: states STG + xg prefetch (t+2) ----
        if (tid < 64) {
            float* sp = sp0 + (size_t)t * HDIM;
            sp[0]      = hn;
            sp[PL]     = r;
            sp[2 * PL] = z;
            sp[3 * PL] = n;
            if (t + 2 < TSTEPS) {
                const float* xq = xgp + (size_t)(t + 2) * GDIM;
                if (cur) { x1r = xq[0]; x1z = xq[HDIM]; x1n = xq[2 * HDIM]; }
                else     { x0r = xq[0]; x0z = xq[HDIM]; x0n = xq[2 * HDIM]; }
            }
        }

        if (!last) cluster_wait_();     // acquire: peers' h writes visible
    }
}

// ---------------------------------------------------------------------------
// Kernel 3: output = h_last @ fc_w + fc_b   (32 x 256, K=256) — tiny
// ---------------------------------------------------------------------------
__global__ __launch_bounds__(256)
void fc_kernel(const float* __restrict__ states,
               const float* __restrict__ fc_w,
               const float* __restrict__ fc_b,
               float* __restrict__ out)
{
    const int b = blockIdx.x;
    const int o = threadIdx.x;
    const float* h = states + (((size_t)b * 4 + 0) * TSTEPS + (TSTEPS - 1)) * HDIM;
    float a0 = 0.f, a1 = 0.f, a2 = 0.f, a3 = 0.f;
#pragma unroll 8
    for (int k = 0; k < HDIM; k += 4) {
        a0 = fmaf(h[k + 0], fc_w[(size_t)(k + 0) * OUTDIM + o], a0);
        a1 = fmaf(h[k + 1], fc_w[(size_t)(k + 1) * OUTDIM + o], a1);
        a2 = fmaf(h[k + 2], fc_w[(size_t)(k + 2) * OUTDIM + o], a2);
        a3 = fmaf(h[k + 3], fc_w[(size_t)(k + 3) * OUTDIM + o], a3);
    }
    out[(size_t)b * OUTDIM + o] = (a0 + a1) + (a2 + a3) + fc_b[o];
}

// ---------------------------------------------------------------------------
// Launch
// ---------------------------------------------------------------------------
extern "C" void kernel_launch(void* const* d_in, const int* in_sizes, int n_in,
                              void* d_out, int out_size)
{
    const float* x    = (const float*)d_in[0];
    const float* Wi   = (const float*)d_in[1];
    const float* Wh   = (const float*)d_in[2];
    const float* bias = (const float*)d_in[3];
    const float* fcw  = (const float*)d_in[4];
    const float* fcb  = (const float*)d_in[5];

    float* out    = (float*)d_out;                 // (32, 256)
    float* states = out + (size_t)BATCH * OUTDIM;  // (32, 4, 2048, 256)

    dim3 ggrid((BATCH * TSTEPS) / 128, GDIM / 64);
    gemm_xg_kernel<<<ggrid, 256>>>(x, Wi, bias);

    gru_rec_kernel<<<BATCH * 4, 384>>>(Wh, states);

    fc_kernel<<<BATCH, 256>>>(states, fcw, fcb, out);
}